// round 14
// baseline (speedup 1.0000x reference)
#include <cuda_runtime.h>
#include <cuda_bf16.h>
#include <cstdint>

#define DIM 128
#define VMAX 50000
#define CMAX 150000
#define EPMAX 200000
#define ENMAX 200000
#define NITER 4
#define NCNT (2 * VMAX + 2 * CMAX)          // 400000
#define SCAN_NBLK ((NCNT + 1023) / 1024)    // 391

// ---------------- static device scratch (no allocations allowed) ----------------
__device__ int   g_pv[EPMAX];
__device__ int   g_pc[EPMAX];
__device__ int   g_nv[ENMAX];
__device__ int   g_nc[ENMAX];
// counts: [vp (VMAX) | vn (VMAX) | cp (CMAX) | cn (CMAX)]
__device__ int   g_cnt[NCNT];
__device__ int   g_off[NCNT];
__device__ int   g_cursor[NCNT];
__device__ int   g_bsum[SCAN_NBLK];
__device__ int   g_csr[2 * EPMAX + 2 * ENMAX];
// double-buffered messages: per buffer [mv_p | mv_n | mc_p | mc_n], each pre-scaled by rsqrt(src deg)
__device__ float g_msg[2 * (size_t)NCNT * DIM];
// pre-split bf16 weight images, B-operand layout [N][K], blocked 8x8 atoms.
// slots: 0-3 W1[seg], 4-7 W2[seg], 8-10 cW parts, 11-13 vW parts. per slot: hi 32KB then lo 32KB.
__device__ unsigned char g_wb[14 * 65536];

// ---------------- helpers ----------------
__device__ __forceinline__ uint32_t smem_u32(const void* p) {
    uint32_t a;
    asm("{ .reg .u64 t; cvta.to.shared.u64 t, %1; cvt.u32.u64 %0, t; }" : "=r"(a) : "l"(p));
    return a;
}

// blocked 8x8 bf16 atom layout for a [128][128] tile: atom = 8 rows x 8 cols = 128B contiguous.
__device__ __forceinline__ uint32_t a_off(int row, int col) {
    return (uint32_t)(((row >> 3) * 16 + (col >> 3)) * 128 + (row & 7) * 16 + (col & 7) * 2);
}

__device__ __forceinline__ void ldsm4(uint32_t* r, uint32_t addr) {
    asm volatile("ldmatrix.sync.aligned.m8n8.x4.shared.b16 {%0,%1,%2,%3}, [%4];"
                 : "=r"(r[0]), "=r"(r[1]), "=r"(r[2]), "=r"(r[3]) : "r"(addr));
}

__device__ __forceinline__ void mma16816(float* c, const uint32_t* a, const uint32_t* b) {
    asm volatile(
        "mma.sync.aligned.m16n8k16.row.col.f32.bf16.bf16.f32 "
        "{%0,%1,%2,%3}, {%4,%5,%6,%7}, {%8,%9}, {%0,%1,%2,%3};"
        : "+f"(c[0]), "+f"(c[1]), "+f"(c[2]), "+f"(c[3])
        : "r"(a[0]), "r"(a[1]), "r"(a[2]), "r"(a[3]), "r"(b[0]), "r"(b[1]));
}

__device__ __forceinline__ uint32_t pack_hi(float x0, float x1, float& r0, float& r1) {
    __nv_bfloat16 h0 = __float2bfloat16(x0), h1 = __float2bfloat16(x1);
    r0 = x0 - __bfloat162float(h0);
    r1 = x1 - __bfloat162float(h1);
    return (uint32_t)__bfloat16_as_ushort(h0) | ((uint32_t)__bfloat16_as_ushort(h1) << 16);
}
__device__ __forceinline__ uint32_t pack_lo(float r0, float r1) {
    __nv_bfloat16 l0 = __float2bfloat16(r0), l1 = __float2bfloat16(r1);
    return (uint32_t)__bfloat16_as_ushort(l0) | ((uint32_t)__bfloat16_as_ushort(l1) << 16);
}

// smem plane offsets (A = X/Y tile, H = hidden tile, B = weights), each plane 32KB
#define SM_AHI 0
#define SM_ALO 32768
#define SM_HHI 65536
#define SM_HLO 98304
#define SM_BHI 131072
#define SM_BLO 163840
#define SM_BYTES 196608

// load 128-row X tile (fp32 global) -> split bf16 hi/lo into blocked smem A planes
__device__ __forceinline__ void load_A(char* smem, const float* __restrict__ X,
                                       int rowbase, int N, int tid, int nthr) {
    for (int i = tid; i < 128 * 32; i += nthr) {
        int row = i >> 5;
        int cg = (i & 31) * 4;
        float4 x = make_float4(0.f, 0.f, 0.f, 0.f);
        int grow = rowbase + row;
        if (grow < N) x = *reinterpret_cast<const float4*>(X + (size_t)grow * DIM + cg);
        float rx, ry, rz, rw;
        uint32_t h01 = pack_hi(x.x, x.y, rx, ry);
        uint32_t h23 = pack_hi(x.z, x.w, rz, rw);
        uint32_t l01 = pack_lo(rx, ry);
        uint32_t l23 = pack_lo(rz, rw);
        uint32_t o = a_off(row, cg);
        *reinterpret_cast<uint2*>(smem + SM_AHI + o) = make_uint2(h01, h23);
        *reinterpret_cast<uint2*>(smem + SM_ALO + o) = make_uint2(l01, l23);
    }
}

// CSR gather-sum 128-row tile of messages -> scale by rsqrt(dest deg) -> split into A planes.
// 8 threads per row (16 floats each), 4 passes of 32 rows.
__device__ __forceinline__ void gather_A(char* smem, const float* __restrict__ slab,
                                         int cntbase, int rowbase, int N, int tid) {
#pragma unroll
    for (int pass = 0; pass < 4; pass++) {
        int row = (tid >> 3) + pass * 32;
        int sub = tid & 7;
        int grow = rowbase + row;
        int deg = 0, off = 0;
        if (grow < N) { deg = g_cnt[cntbase + grow]; off = g_off[cntbase + grow]; }
        float a[16];
#pragma unroll
        for (int q = 0; q < 16; q++) a[q] = 0.f;
        for (int j = 0; j < deg; j++) {
            int s = g_csr[off + j];
            const float4* m = reinterpret_cast<const float4*>(slab + (size_t)s * DIM + sub * 16);
#pragma unroll
            for (int q = 0; q < 4; q++) {
                float4 mv = m[q];
                a[4 * q + 0] += mv.x; a[4 * q + 1] += mv.y;
                a[4 * q + 2] += mv.z; a[4 * q + 3] += mv.w;
            }
        }
        float sc = rsqrtf((float)max(deg, 1));
#pragma unroll
        for (int q = 0; q < 4; q++) {
            float x0 = a[4 * q] * sc, x1 = a[4 * q + 1] * sc;
            float x2 = a[4 * q + 2] * sc, x3 = a[4 * q + 3] * sc;
            float r0, r1, r2, r3;
            uint32_t h01 = pack_hi(x0, x1, r0, r1);
            uint32_t h23 = pack_hi(x2, x3, r2, r3);
            uint32_t o = a_off(row, sub * 16 + q * 4);
            *reinterpret_cast<uint2*>(smem + SM_AHI + o) = make_uint2(h01, h23);
            *reinterpret_cast<uint2*>(smem + SM_ALO + o) = make_uint2(pack_lo(r0, r1), pack_lo(r2, r3));
        }
    }
}

// copy one pre-built 64KB weight image (hi 32KB + lo 32KB) into smem B planes
__device__ __forceinline__ void load_B(char* smem, int slot, int tid, int nthr) {
    const float4* src = reinterpret_cast<const float4*>(g_wb + (size_t)slot * 65536);
    float4* dst = reinterpret_cast<float4*>(smem + SM_BHI);
    for (int i = tid; i < 4096; i += nthr) dst[i] = src[i];
}

// 128x128x128 GEMM, 3-term bf16 split, accumulate into acc[16][4] (warp = 16 rows).
__device__ __forceinline__ void gemm3(uint32_t sA, uint32_t sAlo, uint32_t sB, uint32_t sBlo,
                                      float acc[16][4], int lid, int mr) {
    const int j = lid >> 3, lr = lid & 7;
    const uint32_t ac = (uint32_t)(((mr >> 3) + (j & 1)) * 16 + (j >> 1)) * 128 + lr * 16;
    const uint32_t bc = (uint32_t)((j >> 1) * 16 + (j & 1)) * 128 + lr * 16;
#pragma unroll
    for (int ks = 0; ks < 8; ks++) {
        uint32_t ah[4], al[4];
        ldsm4(ah, sA + ac + ks * 256);
        ldsm4(al, sAlo + ac + ks * 256);
#pragma unroll
        for (int p = 0; p < 8; p++) {
            uint32_t bh[4], bl[4];
            ldsm4(bh, sB + bc + p * 4096 + ks * 256);
            ldsm4(bl, sBlo + bc + p * 4096 + ks * 256);
            mma16816(acc[2 * p],     ah, bh);
            mma16816(acc[2 * p + 1], ah, bh + 2);
            mma16816(acc[2 * p],     al, bh);
            mma16816(acc[2 * p + 1], al, bh + 2);
            mma16816(acc[2 * p],     ah, bl);
            mma16816(acc[2 * p + 1], ah, bl + 2);
        }
    }
}

// ---------------- weight prep: split + transpose + block, once per launch ----------------
__global__ void prep_kernel(const float* __restrict__ W1, const float* __restrict__ W2,
                            const float* __restrict__ cW, const float* __restrict__ vW) {
    int idx = blockIdx.x * blockDim.x + threadIdx.x;
    if (idx >= 14 * 16384) return;
    int slot = idx >> 14;
    int e = idx & 16383;
    int n = e >> 7;     // B row (output col)
    int k = e & 127;    // B col (reduction)
    float w;
    if (slot < 4)       w = W1[(size_t)slot * 16384 + k * 128 + n];
    else if (slot < 8)  w = W2[(size_t)(slot - 4) * 16384 + k * 128 + n];
    else if (slot < 11) w = cW[(size_t)((slot - 8) * 128 + k) * 128 + n];
    else                w = vW[(size_t)((slot - 11) * 128 + k) * 128 + n];
    __nv_bfloat16 h = __float2bfloat16(w);
    __nv_bfloat16 l = __float2bfloat16(w - __bfloat162float(h));
    unsigned char* base = g_wb + (size_t)slot * 65536;
    uint32_t o = a_off(n, k);
    *reinterpret_cast<__nv_bfloat16*>(base + o) = h;
    *reinterpret_cast<__nv_bfloat16*>(base + 32768 + o) = l;
}

// ---------------- CSR build ----------------
__global__ void count_kernel(const int* __restrict__ eidx,
                             const int* __restrict__ vI, const int* __restrict__ cI,
                             int ne, int vbase, int cbase,
                             int* __restrict__ ev, int* __restrict__ ec) {
    int e = blockIdx.x * blockDim.x + threadIdx.x;
    if (e >= ne) return;
    int ed = eidx[e];
    int v = vI[ed];
    int c = cI[ed];
    ev[e] = v; ec[e] = c;
    atomicAdd(g_cnt + vbase + v, 1);
    atomicAdd(g_cnt + cbase + c, 1);
}

// exclusive scan over g_cnt (1024 elems / block of 256 threads)
__global__ __launch_bounds__(256) void scan1_kernel() {
    __shared__ int wsum[8];
    int b = blockIdx.x, t = threadIdx.x;
    int base = b * 1024 + t * 4;
    int v[4];
#pragma unroll
    for (int i = 0; i < 4; i++) v[i] = (base + i < NCNT) ? g_cnt[base + i] : 0;
    int ts = v[0] + v[1] + v[2] + v[3];
    int lane = t & 31, wid = t >> 5;
    int inc = ts;
#pragma unroll
    for (int d = 1; d < 32; d <<= 1) { int n = __shfl_up_sync(~0u, inc, d); if (lane >= d) inc += n; }
    if (lane == 31) wsum[wid] = inc;
    __syncthreads();
    if (wid == 0) {
        int s = (lane < 8) ? wsum[lane] : 0;
#pragma unroll
        for (int d = 1; d < 8; d <<= 1) { int n = __shfl_up_sync(~0u, s, d); if (lane >= d) s += n; }
        if (lane < 8) wsum[lane] = s;   // inclusive warp sums
    }
    __syncthreads();
    int woff = (wid == 0) ? 0 : wsum[wid - 1];
    int run = woff + inc - ts;   // exclusive offset for this thread
#pragma unroll
    for (int i = 0; i < 4; i++) { if (base + i < NCNT) g_off[base + i] = run; run += v[i]; }
    if (t == 255) g_bsum[b] = run;   // block total
}

__global__ __launch_bounds__(512) void scan2_kernel() {
    __shared__ int ws[16];
    int t = threadIdx.x;
    int v = (t < SCAN_NBLK) ? g_bsum[t] : 0;
    int lane = t & 31, wid = t >> 5;
    int inc = v;
#pragma unroll
    for (int d = 1; d < 32; d <<= 1) { int n = __shfl_up_sync(~0u, inc, d); if (lane >= d) inc += n; }
    if (lane == 31) ws[wid] = inc;
    __syncthreads();
    if (wid == 0) {
        int s = (lane < 16) ? ws[lane] : 0;
#pragma unroll
        for (int d = 1; d < 16; d <<= 1) { int n = __shfl_up_sync(~0u, s, d); if (lane >= d) s += n; }
        if (lane < 16) ws[lane] = s;
    }
    __syncthreads();
    int woff = (wid == 0) ? 0 : ws[wid - 1];
    if (t < SCAN_NBLK) g_bsum[t] = woff + inc - v;   // exclusive
}

__global__ void scan3_kernel() {
    int i = blockIdx.x * blockDim.x + threadIdx.x;
    if (i >= NCNT) return;
    int o = g_off[i] + g_bsum[i >> 10];
    g_off[i] = o;
    g_cursor[i] = o;
}

__global__ void fill_kernel(const int* __restrict__ ev, const int* __restrict__ ec,
                            int ne, int vbase, int cbase) {
    int e = blockIdx.x * blockDim.x + threadIdx.x;
    if (e >= ne) return;
    int v = ev[e], c = ec[e];
    int p1 = atomicAdd(g_cursor + vbase + v, 1);
    g_csr[p1] = c;                                  // var's incident clause (c2v source)
    int p2 = atomicAdd(g_cursor + cbase + c, 1);
    g_csr[p2] = v;                                  // clause's incident var (v2c source)
}

// ---------------- iter-0 message MLP (standalone; subsequent iters fused) ----------------
__global__ __launch_bounds__(256) void mlp_tc_kernel(
    const float* __restrict__ vt, const float* __restrict__ ct, int V, int C,
    const float* __restrict__ b1, const float* __restrict__ b2,
    float* __restrict__ msgbase, int vtiles) {
    extern __shared__ char smem[];
    const uint32_t sb = smem_u32(smem);

    const int bx = blockIdx.x;
    const bool isv = (bx < vtiles);
    const int local = isv ? bx : bx - vtiles;
    const float* X = isv ? vt : ct;
    const int N = isv ? V : C;

    const int tid = threadIdx.x;
    const int wid = tid >> 5;
    const int lid = tid & 31;
    const int mr = wid * 16;
    const int rowbase = local * 128;
    const int row0 = mr + (lid >> 2);
    const int c0l = (lid & 3) * 2;
    const int g0 = rowbase + row0;
    const int g1 = g0 + 8;

    load_A(smem, X, rowbase, N, tid, 256);

    float acc[16][4];
#pragma unroll
    for (int pol = 0; pol < 2; pol++) {
        const int seg = (isv ? 0 : 2) + pol;
        const float* bb1 = b1 + seg * DIM;
        const float* bb2 = b2 + seg * DIM;
        float* Y = msgbase + ((seg == 0) ? (size_t)0
                     : (seg == 1) ? (size_t)VMAX * DIM
                     : (seg == 2) ? (size_t)2 * VMAX * DIM
                                  : ((size_t)2 * VMAX + CMAX) * DIM);
        const int cntbase = (seg == 0) ? 0 : (seg == 1) ? VMAX
                          : (seg == 2) ? 2 * VMAX : 2 * VMAX + CMAX;

        __syncthreads();
        load_B(smem, seg, tid, 256);           // W1[seg]
        __syncthreads();

#pragma unroll
        for (int t = 0; t < 16; t++)
#pragma unroll
            for (int q = 0; q < 4; q++) acc[t][q] = 0.f;
        gemm3(sb + SM_AHI, sb + SM_ALO, sb + SM_BHI, sb + SM_BLO, acc, lid, mr);

#pragma unroll
        for (int nt = 0; nt < 16; nt++) {
            int col = nt * 8 + c0l;
            float2 bb = *reinterpret_cast<const float2*>(bb1 + col);
            float x0 = fmaxf(acc[nt][0] + bb.x, 0.f);
            float x1 = fmaxf(acc[nt][1] + bb.y, 0.f);
            float x2 = fmaxf(acc[nt][2] + bb.x, 0.f);
            float x3 = fmaxf(acc[nt][3] + bb.y, 0.f);
            float r0, r1, r2, r3;
            uint32_t oA = a_off(row0, col);
            uint32_t oB = a_off(row0 + 8, col);
            uint32_t h01 = pack_hi(x0, x1, r0, r1);
            uint32_t h23 = pack_hi(x2, x3, r2, r3);
            *reinterpret_cast<uint32_t*>(smem + SM_HHI + oA) = h01;
            *reinterpret_cast<uint32_t*>(smem + SM_HLO + oA) = pack_lo(r0, r1);
            *reinterpret_cast<uint32_t*>(smem + SM_HHI + oB) = h23;
            *reinterpret_cast<uint32_t*>(smem + SM_HLO + oB) = pack_lo(r2, r3);
#pragma unroll
            for (int q = 0; q < 4; q++) acc[nt][q] = 0.f;
        }
        __syncthreads();
        load_B(smem, 4 + seg, tid, 256);       // W2[seg]
        __syncthreads();

        gemm3(sb + SM_HHI, sb + SM_HLO, sb + SM_BHI, sb + SM_BLO, acc, lid, mr);

        float s0 = 0.f, s1 = 0.f;
        if (g0 < N) s0 = rsqrtf((float)max(g_cnt[cntbase + g0], 1));
        if (g1 < N) s1 = rsqrtf((float)max(g_cnt[cntbase + g1], 1));
#pragma unroll
        for (int nt = 0; nt < 16; nt++) {
            int col = nt * 8 + c0l;
            float2 bb = *reinterpret_cast<const float2*>(bb2 + col);
            if (g0 < N)
                *reinterpret_cast<float2*>(Y + (size_t)g0 * DIM + col) =
                    make_float2((acc[nt][0] + bb.x) * s0, (acc[nt][1] + bb.y) * s0);
            if (g1 < N)
                *reinterpret_cast<float2*>(Y + (size_t)g1 * DIM + col) =
                    make_float2((acc[nt][2] + bb.x) * s1, (acc[nt][3] + bb.y) * s1);
        }
    }
}

// ---------------- fused per-iteration kernel ----------------
// grid = ctiles + vtiles. Per CTA (128 dest rows):
//   upd: seg0 load_A(emb), seg1/2 gather_A(CSR-sum msgs_in) -> 3x gemm3 -> Y = acc + bias
//   epilogue: store Y to emb_out; if do_mlp, split Y into A planes and run both
//   polarity message MLPs (2x2 gemm3), storing msgs_out scaled by rsqrt(src deg).
__global__ __launch_bounds__(256) void iter_kernel(
    const float* __restrict__ vt, const float* __restrict__ ct, int V, int C, int ctiles,
    const float* __restrict__ cb, const float* __restrict__ vb,
    float* __restrict__ v_out, float* __restrict__ c_out,
    const float* __restrict__ msg_in, float* __restrict__ msg_out,
    const float* __restrict__ b1, const float* __restrict__ b2, int do_mlp) {
    extern __shared__ char smem[];
    const uint32_t sb = smem_u32(smem);

    const int bx = blockIdx.x;
    const bool isc = (bx < ctiles);
    const int local = isc ? bx : bx - ctiles;

    const float* X     = isc ? ct : vt;
    const int N        = isc ? C : V;
    const int slotW    = isc ? 8 : 11;
    const float* bias  = isc ? cb : vb;
    float* Yout        = isc ? c_out : v_out;
    // gather inputs: c-update reads v-messages; v-update reads c-messages
    const float* in_p  = msg_in + (isc ? (size_t)0 : (size_t)2 * VMAX * DIM);
    const float* in_n  = msg_in + (isc ? (size_t)VMAX * DIM : ((size_t)2 * VMAX + CMAX) * DIM);
    const int dbase_p  = isc ? 2 * VMAX : 0;
    const int dbase_n  = isc ? 2 * VMAX + CMAX : VMAX;
    const int mlpseg0  = isc ? 2 : 0;
    float* out_p       = msg_out + (isc ? (size_t)2 * VMAX * DIM : (size_t)0);
    float* out_n       = msg_out + (isc ? ((size_t)2 * VMAX + CMAX) * DIM : (size_t)VMAX * DIM);

    const int tid = threadIdx.x;
    const int wid = tid >> 5;
    const int lid = tid & 31;
    const int mr = wid * 16;
    const int rowbase = local * 128;
    const int row0 = mr + (lid >> 2);
    const int c0l = (lid & 3) * 2;
    const int g0 = rowbase + row0;
    const int g1 = g0 + 8;

    float acc[16][4];
#pragma unroll
    for (int t = 0; t < 16; t++)
#pragma unroll
        for (int q = 0; q < 4; q++) acc[t][q] = 0.f;

    // ---- update GEMM: K = 384 over [emb | p-agg | n-agg] ----
#pragma unroll
    for (int s = 0; s < 3; s++) {
        __syncthreads();           // previous gemm3's A/B readers done
        if (s == 0)      load_A(smem, X, rowbase, N, tid, 256);
        else if (s == 1) gather_A(smem, in_p, dbase_p, rowbase, N, tid);
        else             gather_A(smem, in_n, dbase_n, rowbase, N, tid);
        load_B(smem, slotW + s, tid, 256);
        __syncthreads();
        gemm3(sb + SM_AHI, sb + SM_ALO, sb + SM_BHI, sb + SM_BLO, acc, lid, mr);
    }
    __syncthreads();               // all gemm3 A-readers done before epilogue rewrites A

    // ---- epilogue: Y = acc + bias -> global emb_out (+ split into A planes for fused MLP)
#pragma unroll
    for (int nt = 0; nt < 16; nt++) {
        int col = nt * 8 + c0l;
        float2 bb = *reinterpret_cast<const float2*>(bias + col);
        float y0 = acc[nt][0] + bb.x, y1 = acc[nt][1] + bb.y;
        float y2 = acc[nt][2] + bb.x, y3 = acc[nt][3] + bb.y;
        if (g0 < N) *reinterpret_cast<float2*>(Yout + (size_t)g0 * DIM + col) = make_float2(y0, y1);
        if (g1 < N) *reinterpret_cast<float2*>(Yout + (size_t)g1 * DIM + col) = make_float2(y2, y3);
        if (do_mlp) {
            float r0, r1, r2, r3;
            uint32_t oA = a_off(row0, col);
            uint32_t oB = a_off(row0 + 8, col);
            uint32_t h01 = pack_hi(y0, y1, r0, r1);
            uint32_t h23 = pack_hi(y2, y3, r2, r3);
            *reinterpret_cast<uint32_t*>(smem + SM_AHI + oA) = h01;
            *reinterpret_cast<uint32_t*>(smem + SM_ALO + oA) = pack_lo(r0, r1);
            *reinterpret_cast<uint32_t*>(smem + SM_AHI + oB) = h23;
            *reinterpret_cast<uint32_t*>(smem + SM_ALO + oB) = pack_lo(r2, r3);
        }
    }
    if (!do_mlp) return;

    // ---- fused next-iteration message MLPs (both polarities) on Y in A planes ----
#pragma unroll
    for (int pol = 0; pol < 2; pol++) {
        const int seg = mlpseg0 + pol;
        const float* bb1 = b1 + seg * DIM;
        const float* bb2 = b2 + seg * DIM;
        float* Y = pol ? out_n : out_p;
        const int cntbase = pol ? dbase_n : dbase_p;   // dest-node deg == next-iter src deg

        __syncthreads();           // A-plane writes visible; prior B readers done
        load_B(smem, seg, tid, 256);           // W1[seg]
        __syncthreads();

#pragma unroll
        for (int t = 0; t < 16; t++)
#pragma unroll
            for (int q = 0; q < 4; q++) acc[t][q] = 0.f;
        gemm3(sb + SM_AHI, sb + SM_ALO, sb + SM_BHI, sb + SM_BLO, acc, lid, mr);

#pragma unroll
        for (int nt = 0; nt < 16; nt++) {
            int col = nt * 8 + c0l;
            float2 bb = *reinterpret_cast<const float2*>(bb1 + col);
            float x0 = fmaxf(acc[nt][0] + bb.x, 0.f);
            float x1 = fmaxf(acc[nt][1] + bb.y, 0.f);
            float x2 = fmaxf(acc[nt][2] + bb.x, 0.f);
            float x3 = fmaxf(acc[nt][3] + bb.y, 0.f);
            float r0, r1, r2, r3;
            uint32_t oA = a_off(row0, col);
            uint32_t oB = a_off(row0 + 8, col);
            uint32_t h01 = pack_hi(x0, x1, r0, r1);
            uint32_t h23 = pack_hi(x2, x3, r2, r3);
            *reinterpret_cast<uint32_t*>(smem + SM_HHI + oA) = h01;
            *reinterpret_cast<uint32_t*>(smem + SM_HLO + oA) = pack_lo(r0, r1);
            *reinterpret_cast<uint32_t*>(smem + SM_HHI + oB) = h23;
            *reinterpret_cast<uint32_t*>(smem + SM_HLO + oB) = pack_lo(r2, r3);
#pragma unroll
            for (int q = 0; q < 4; q++) acc[nt][q] = 0.f;
        }
        __syncthreads();           // H writes visible; W1 readers done
        load_B(smem, 4 + seg, tid, 256);       // W2[seg]
        __syncthreads();

        gemm3(sb + SM_HHI, sb + SM_HLO, sb + SM_BHI, sb + SM_BLO, acc, lid, mr);

        float s0 = 0.f, s1 = 0.f;
        if (g0 < N) s0 = rsqrtf((float)max(g_cnt[cntbase + g0], 1));
        if (g1 < N) s1 = rsqrtf((float)max(g_cnt[cntbase + g1], 1));
#pragma unroll
        for (int nt = 0; nt < 16; nt++) {
            int col = nt * 8 + c0l;
            float2 bb = *reinterpret_cast<const float2*>(bb2 + col);
            if (g0 < N)
                *reinterpret_cast<float2*>(Y + (size_t)g0 * DIM + col) =
                    make_float2((acc[nt][0] + bb.x) * s0, (acc[nt][1] + bb.y) * s0);
            if (g1 < N)
                *reinterpret_cast<float2*>(Y + (size_t)g1 * DIM + col) =
                    make_float2((acc[nt][2] + bb.x) * s1, (acc[nt][3] + bb.y) * s1);
        }
    }
}

// ---------------- host launcher ----------------
extern "C" void kernel_launch(void* const* d_in, const int* in_sizes, int n_in,
                              void* d_out, int out_size) {
    int base = (in_sizes[0] == 1 && in_sizes[1] == 1) ? 2 : 0;
    const int*   v_edge = (const int*)d_in[base + 0];
    const int*   c_edge = (const int*)d_in[base + 1];
    const int*   p_idx  = (const int*)d_in[base + 2];
    const int*   n_idx  = (const int*)d_in[base + 3];
    const float* v_emb  = (const float*)d_in[base + 4];
    const float* c_emb  = (const float*)d_in[base + 5];
    const float* W1     = (const float*)d_in[base + 6];
    const float* b1     = (const float*)d_in[base + 7];
    const float* W2     = (const float*)d_in[base + 8];
    const float* b2     = (const float*)d_in[base + 9];
    const float* cW     = (const float*)d_in[base + 10];
    const float* cb     = (const float*)d_in[base + 11];
    const float* vW     = (const float*)d_in[base + 12];
    const float* vbias  = (const float*)d_in[base + 13];

    const int EP = in_sizes[base + 2];
    const int EN = in_sizes[base + 3];
    const int V  = in_sizes[base + 4] / DIM;
    const int C  = in_sizes[base + 5] / DIM;

    int *pv, *pc, *nv, *nc, *cnt;
    float *msg;
    cudaGetSymbolAddress((void**)&pv,  g_pv);
    cudaGetSymbolAddress((void**)&pc,  g_pc);
    cudaGetSymbolAddress((void**)&nv,  g_nv);
    cudaGetSymbolAddress((void**)&nc,  g_nc);
    cudaGetSymbolAddress((void**)&cnt, g_cnt);
    cudaGetSymbolAddress((void**)&msg, g_msg);

    float* msgbuf[2] = { msg, msg + (size_t)NCNT * DIM };

    cudaFuncSetAttribute(mlp_tc_kernel, cudaFuncAttributeMaxDynamicSharedMemorySize, SM_BYTES);
    cudaFuncSetAttribute(iter_kernel,   cudaFuncAttributeMaxDynamicSharedMemorySize, SM_BYTES);

    // one-time per call: weight prep + CSR build
    prep_kernel<<<(14 * 16384 + 255) / 256, 256>>>(W1, W2, cW, vW);
    cudaMemsetAsync(cnt, 0, (size_t)NCNT * sizeof(int));
    count_kernel<<<(EP + 255) / 256, 256>>>(p_idx, v_edge, c_edge, EP, 0, 2 * VMAX, pv, pc);
    count_kernel<<<(EN + 255) / 256, 256>>>(n_idx, v_edge, c_edge, EN, VMAX, 2 * VMAX + CMAX, nv, nc);
    scan1_kernel<<<SCAN_NBLK, 256>>>();
    scan2_kernel<<<1, 512>>>();
    scan3_kernel<<<(NCNT + 255) / 256, 256>>>();
    fill_kernel<<<(EP + 255) / 256, 256>>>(pv, pc, EP, 0, 2 * VMAX);
    fill_kernel<<<(EN + 255) / 256, 256>>>(nv, nc, EN, VMAX, 2 * VMAX + CMAX);

    // output slab doubles as the embedding history: [5,V,128] then [5,C,128]
    float* out   = (float*)d_out;
    float* out_v = out;
    float* out_c = out + (size_t)(NITER + 1) * V * DIM;
    cudaMemcpyAsync(out_v, v_emb, (size_t)V * DIM * sizeof(float), cudaMemcpyDeviceToDevice);
    cudaMemcpyAsync(out_c, c_emb, (size_t)C * DIM * sizeof(float), cudaMemcpyDeviceToDevice);

    const int vtiles = (V + 127) / 128;
    const int ctiles = (C + 127) / 128;

    // iter-0 messages from the initial embeddings -> buffer 0
    mlp_tc_kernel<<<vtiles + ctiles, 256, SM_BYTES>>>(out_v, out_c, V, C, b1, b2, msgbuf[0], vtiles);

    for (int t = 0; t < NITER; t++) {
        const float* vt = out_v + (size_t)t * V * DIM;
        const float* ct = out_c + (size_t)t * C * DIM;
        iter_kernel<<<ctiles + vtiles, 256, SM_BYTES>>>(
            vt, ct, V, C, ctiles, cb, vbias,
            out_v + (size_t)(t + 1) * V * DIM, out_c + (size_t)(t + 1) * C * DIM,
            msgbuf[t & 1], msgbuf[(t + 1) & 1], b1, b2, (t < NITER - 1) ? 1 : 0);
    }
}

// round 17
// speedup vs baseline: 1.2500x; 1.2500x over previous
#include <cuda_runtime.h>
#include <cuda_bf16.h>
#include <cstdint>

#define DIM 128
#define VMAX 50000
#define CMAX 150000
#define EPMAX 200000
#define ENMAX 200000
#define NITER 4
#define NCNT (2 * VMAX + 2 * CMAX)          // 400000
#define SCAN_NBLK ((NCNT + 1023) / 1024)    // 391

// ---------------- static device scratch (no allocations allowed) ----------------
__device__ int   g_pv[EPMAX];
__device__ int   g_pc[EPMAX];
__device__ int   g_nv[ENMAX];
__device__ int   g_nc[ENMAX];
// counts: [vp (VMAX) | vn (VMAX) | cp (CMAX) | cn (CMAX)]
__device__ int   g_cnt[NCNT];
__device__ int   g_off[NCNT];
__device__ int   g_cursor[NCNT];
__device__ int   g_bsum[SCAN_NBLK];
__device__ int   g_csr[2 * EPMAX + 2 * ENMAX];
// double-buffered messages: per buffer [mv_p | mv_n | mc_p | mc_n], each pre-scaled by rsqrt(src deg)
__device__ float g_msg[2 * (size_t)NCNT * DIM];
// pre-split bf16 weight images, B-operand layout [N][K], blocked 8x8 atoms.
// slots: 0-3 W1[seg], 4-7 W2[seg], 8-10 cW parts, 11-13 vW parts. per slot: hi 32KB then lo 32KB.
__device__ unsigned char g_wb[14 * 65536];

// ---------------- helpers ----------------
__device__ __forceinline__ uint32_t smem_u32(const void* p) {
    uint32_t a;
    asm("{ .reg .u64 t; cvta.to.shared.u64 t, %1; cvt.u32.u64 %0, t; }" : "=r"(a) : "l"(p));
    return a;
}

// blocked 8x8 bf16 atom layout for a [128][128] tile: atom = 8 rows x 8 cols = 128B contiguous.
__device__ __forceinline__ uint32_t a_off(int row, int col) {
    return (uint32_t)(((row >> 3) * 16 + (col >> 3)) * 128 + (row & 7) * 16 + (col & 7) * 2);
}

__device__ __forceinline__ void ldsm4(uint32_t* r, uint32_t addr) {
    asm volatile("ldmatrix.sync.aligned.m8n8.x4.shared.b16 {%0,%1,%2,%3}, [%4];"
                 : "=r"(r[0]), "=r"(r[1]), "=r"(r[2]), "=r"(r[3]) : "r"(addr));
}

__device__ __forceinline__ void mma16816(float* c, const uint32_t* a, const uint32_t* b) {
    asm volatile(
        "mma.sync.aligned.m16n8k16.row.col.f32.bf16.bf16.f32 "
        "{%0,%1,%2,%3}, {%4,%5,%6,%7}, {%8,%9}, {%0,%1,%2,%3};"
        : "+f"(c[0]), "+f"(c[1]), "+f"(c[2]), "+f"(c[3])
        : "r"(a[0]), "r"(a[1]), "r"(a[2]), "r"(a[3]), "r"(b[0]), "r"(b[1]));
}

__device__ __forceinline__ uint32_t pack_hi(float x0, float x1, float& r0, float& r1) {
    __nv_bfloat16 h0 = __float2bfloat16(x0), h1 = __float2bfloat16(x1);
    r0 = x0 - __bfloat162float(h0);
    r1 = x1 - __bfloat162float(h1);
    return (uint32_t)__bfloat16_as_ushort(h0) | ((uint32_t)__bfloat16_as_ushort(h1) << 16);
}
__device__ __forceinline__ uint32_t pack_lo(float r0, float r1) {
    __nv_bfloat16 l0 = __float2bfloat16(r0), l1 = __float2bfloat16(r1);
    return (uint32_t)__bfloat16_as_ushort(l0) | ((uint32_t)__bfloat16_as_ushort(l1) << 16);
}

// smem plane offsets: A hi | A lo (X/Y or H overlaid) | single B plane (one split half)
#define SM_AHI 0
#define SM_ALO 32768
#define SM_B   65536
#define SM_BYTES 98304

// load 128-row X tile (fp32 global) -> split bf16 hi/lo into blocked smem A planes
__device__ __forceinline__ void load_A(char* smem, const float* __restrict__ X,
                                       int rowbase, int N, int tid, int nthr) {
    for (int i = tid; i < 128 * 32; i += nthr) {
        int row = i >> 5;
        int cg = (i & 31) * 4;
        float4 x = make_float4(0.f, 0.f, 0.f, 0.f);
        int grow = rowbase + row;
        if (grow < N) x = *reinterpret_cast<const float4*>(X + (size_t)grow * DIM + cg);
        float rx, ry, rz, rw;
        uint32_t h01 = pack_hi(x.x, x.y, rx, ry);
        uint32_t h23 = pack_hi(x.z, x.w, rz, rw);
        uint32_t l01 = pack_lo(rx, ry);
        uint32_t l23 = pack_lo(rz, rw);
        uint32_t o = a_off(row, cg);
        *reinterpret_cast<uint2*>(smem + SM_AHI + o) = make_uint2(h01, h23);
        *reinterpret_cast<uint2*>(smem + SM_ALO + o) = make_uint2(l01, l23);
    }
}

// CSR gather-sum 128-row tile of messages -> scale by rsqrt(dest deg) -> split into A planes.
// 8 threads per row (16 floats each), 4 passes of 32 rows.
__device__ __forceinline__ void gather_A(char* smem, const float* __restrict__ slab,
                                         int cntbase, int rowbase, int N, int tid) {
#pragma unroll
    for (int pass = 0; pass < 4; pass++) {
        int row = (tid >> 3) + pass * 32;
        int sub = tid & 7;
        int grow = rowbase + row;
        int deg = 0, off = 0;
        if (grow < N) { deg = g_cnt[cntbase + grow]; off = g_off[cntbase + grow]; }
        float a[16];
#pragma unroll
        for (int q = 0; q < 16; q++) a[q] = 0.f;
        for (int j = 0; j < deg; j++) {
            int s = g_csr[off + j];
            const float4* m = reinterpret_cast<const float4*>(slab + (size_t)s * DIM + sub * 16);
#pragma unroll
            for (int q = 0; q < 4; q++) {
                float4 mv = m[q];
                a[4 * q + 0] += mv.x; a[4 * q + 1] += mv.y;
                a[4 * q + 2] += mv.z; a[4 * q + 3] += mv.w;
            }
        }
        float sc = rsqrtf((float)max(deg, 1));
#pragma unroll
        for (int q = 0; q < 4; q++) {
            float x0 = a[4 * q] * sc, x1 = a[4 * q + 1] * sc;
            float x2 = a[4 * q + 2] * sc, x3 = a[4 * q + 3] * sc;
            float r0, r1, r2, r3;
            uint32_t h01 = pack_hi(x0, x1, r0, r1);
            uint32_t h23 = pack_hi(x2, x3, r2, r3);
            uint32_t o = a_off(row, sub * 16 + q * 4);
            *reinterpret_cast<uint2*>(smem + SM_AHI + o) = make_uint2(h01, h23);
            *reinterpret_cast<uint2*>(smem + SM_ALO + o) = make_uint2(pack_lo(r0, r1), pack_lo(r2, r3));
        }
    }
}

// copy one 32KB half (0=hi, 1=lo) of a weight image into the single smem B plane
__device__ __forceinline__ void load_Bhalf(char* smem, int slot, int half, int tid) {
    const float4* src = reinterpret_cast<const float4*>(
        g_wb + (size_t)slot * 65536 + (size_t)half * 32768);
    float4* dst = reinterpret_cast<float4*>(smem + SM_B);
#pragma unroll
    for (int i = 0; i < 8; i++) dst[tid + 256 * i] = src[tid + 256 * i];
}

// (Ah + Al) x B : 4 mma per p-tile
__device__ __forceinline__ void gemm_pair(uint32_t sA, uint32_t sAlo, uint32_t sB,
                                          float acc[16][4], int lid, int mr) {
    const int j = lid >> 3, lr = lid & 7;
    const uint32_t ac = (uint32_t)(((mr >> 3) + (j & 1)) * 16 + (j >> 1)) * 128 + lr * 16;
    const uint32_t bc = (uint32_t)((j >> 1) * 16 + (j & 1)) * 128 + lr * 16;
#pragma unroll
    for (int ks = 0; ks < 8; ks++) {
        uint32_t ah[4], al[4];
        ldsm4(ah, sA + ac + ks * 256);
        ldsm4(al, sAlo + ac + ks * 256);
#pragma unroll
        for (int p = 0; p < 8; p++) {
            uint32_t b[4];
            ldsm4(b, sB + bc + p * 4096 + ks * 256);
            mma16816(acc[2 * p],     ah, b);
            mma16816(acc[2 * p + 1], ah, b + 2);
            mma16816(acc[2 * p],     al, b);
            mma16816(acc[2 * p + 1], al, b + 2);
        }
    }
}

// Ah x B : 2 mma per p-tile
__device__ __forceinline__ void gemm_single(uint32_t sA, uint32_t sB,
                                            float acc[16][4], int lid, int mr) {
    const int j = lid >> 3, lr = lid & 7;
    const uint32_t ac = (uint32_t)(((mr >> 3) + (j & 1)) * 16 + (j >> 1)) * 128 + lr * 16;
    const uint32_t bc = (uint32_t)((j >> 1) * 16 + (j & 1)) * 128 + lr * 16;
#pragma unroll
    for (int ks = 0; ks < 8; ks++) {
        uint32_t ah[4];
        ldsm4(ah, sA + ac + ks * 256);
#pragma unroll
        for (int p = 0; p < 8; p++) {
            uint32_t b[4];
            ldsm4(b, sB + bc + p * 4096 + ks * 256);
            mma16816(acc[2 * p],     ah, b);
            mma16816(acc[2 * p + 1], ah, b + 2);
        }
    }
}

// ---------------- weight prep: split + transpose + block, once per launch ----------------
__global__ void prep_kernel(const float* __restrict__ W1, const float* __restrict__ W2,
                            const float* __restrict__ cW, const float* __restrict__ vW) {
    int idx = blockIdx.x * blockDim.x + threadIdx.x;
    if (idx >= 14 * 16384) return;
    int slot = idx >> 14;
    int e = idx & 16383;
    int n = e >> 7;     // B row (output col)
    int k = e & 127;    // B col (reduction)
    float w;
    if (slot < 4)       w = W1[(size_t)slot * 16384 + k * 128 + n];
    else if (slot < 8)  w = W2[(size_t)(slot - 4) * 16384 + k * 128 + n];
    else if (slot < 11) w = cW[(size_t)((slot - 8) * 128 + k) * 128 + n];
    else                w = vW[(size_t)((slot - 11) * 128 + k) * 128 + n];
    __nv_bfloat16 h = __float2bfloat16(w);
    __nv_bfloat16 l = __float2bfloat16(w - __bfloat162float(h));
    unsigned char* base = g_wb + (size_t)slot * 65536;
    uint32_t o = a_off(n, k);
    *reinterpret_cast<__nv_bfloat16*>(base + o) = h;
    *reinterpret_cast<__nv_bfloat16*>(base + 32768 + o) = l;
}

// ---------------- CSR build ----------------
__global__ void count_kernel(const int* __restrict__ eidx,
                             const int* __restrict__ vI, const int* __restrict__ cI,
                             int ne, int vbase, int cbase,
                             int* __restrict__ ev, int* __restrict__ ec) {
    int e = blockIdx.x * blockDim.x + threadIdx.x;
    if (e >= ne) return;
    int ed = eidx[e];
    int v = vI[ed];
    int c = cI[ed];
    ev[e] = v; ec[e] = c;
    atomicAdd(g_cnt + vbase + v, 1);
    atomicAdd(g_cnt + cbase + c, 1);
}

// exclusive scan over g_cnt (1024 elems / block of 256 threads)
__global__ __launch_bounds__(256) void scan1_kernel() {
    __shared__ int wsum[8];
    int b = blockIdx.x, t = threadIdx.x;
    int base = b * 1024 + t * 4;
    int v[4];
#pragma unroll
    for (int i = 0; i < 4; i++) v[i] = (base + i < NCNT) ? g_cnt[base + i] : 0;
    int ts = v[0] + v[1] + v[2] + v[3];
    int lane = t & 31, wid = t >> 5;
    int inc = ts;
#pragma unroll
    for (int d = 1; d < 32; d <<= 1) { int n = __shfl_up_sync(~0u, inc, d); if (lane >= d) inc += n; }
    if (lane == 31) wsum[wid] = inc;
    __syncthreads();
    if (wid == 0) {
        int s = (lane < 8) ? wsum[lane] : 0;
#pragma unroll
        for (int d = 1; d < 8; d <<= 1) { int n = __shfl_up_sync(~0u, s, d); if (lane >= d) s += n; }
        if (lane < 8) wsum[lane] = s;   // inclusive warp sums
    }
    __syncthreads();
    int woff = (wid == 0) ? 0 : wsum[wid - 1];
    int run = woff + inc - ts;   // exclusive offset for this thread
#pragma unroll
    for (int i = 0; i < 4; i++) { if (base + i < NCNT) g_off[base + i] = run; run += v[i]; }
    if (t == 255) g_bsum[b] = run;   // block total
}

__global__ __launch_bounds__(512) void scan2_kernel() {
    __shared__ int ws[16];
    int t = threadIdx.x;
    int v = (t < SCAN_NBLK) ? g_bsum[t] : 0;
    int lane = t & 31, wid = t >> 5;
    int inc = v;
#pragma unroll
    for (int d = 1; d < 32; d <<= 1) { int n = __shfl_up_sync(~0u, inc, d); if (lane >= d) inc += n; }
    if (lane == 31) ws[wid] = inc;
    __syncthreads();
    if (wid == 0) {
        int s = (lane < 16) ? ws[lane] : 0;
#pragma unroll
        for (int d = 1; d < 16; d <<= 1) { int n = __shfl_up_sync(~0u, s, d); if (lane >= d) s += n; }
        if (lane < 16) ws[lane] = s;
    }
    __syncthreads();
    int woff = (wid == 0) ? 0 : ws[wid - 1];
    if (t < SCAN_NBLK) g_bsum[t] = woff + inc - v;   // exclusive
}

__global__ void scan3_kernel() {
    int i = blockIdx.x * blockDim.x + threadIdx.x;
    if (i >= NCNT) return;
    int o = g_off[i] + g_bsum[i >> 10];
    g_off[i] = o;
    g_cursor[i] = o;
}

__global__ void fill_kernel(const int* __restrict__ ev, const int* __restrict__ ec,
                            int ne, int vbase, int cbase) {
    int e = blockIdx.x * blockDim.x + threadIdx.x;
    if (e >= ne) return;
    int v = ev[e], c = ec[e];
    int p1 = atomicAdd(g_cursor + vbase + v, 1);
    g_csr[p1] = c;                                  // var's incident clause (c2v source)
    int p2 = atomicAdd(g_cursor + cbase + c, 1);
    g_csr[p2] = v;                                  // clause's incident var (v2c source)
}

// ---------------- shared MLP sub-phase: 2-layer MLP on X (global) -> msg slab ----------------
// Reads X rows [rowbase,rowbase+128) from global, overlays H on the A planes,
// stores (MLP(X)) * rsqrt(deg) to Y. Caller must sync before (prior smem readers done).
__device__ __forceinline__ void run_mlp_pol(
    char* smem, uint32_t sb, const float* __restrict__ Xg, int N, int rowbase,
    int seg, const float* __restrict__ b1, const float* __restrict__ b2,
    float* __restrict__ Y, int cntbase, float acc[16][4],
    int tid, int lid, int mr, int row0, int c0l, int g0, int g1) {
    const float* bb1 = b1 + seg * DIM;
    const float* bb2 = b2 + seg * DIM;

    load_A(smem, Xg, rowbase, N, tid, 256);
    load_Bhalf(smem, seg, 0, tid);             // W1 hi
    __syncthreads();
#pragma unroll
    for (int t = 0; t < 16; t++)
#pragma unroll
        for (int q = 0; q < 4; q++) acc[t][q] = 0.f;
    gemm_pair(sb + SM_AHI, sb + SM_ALO, sb + SM_B, acc, lid, mr);
    __syncthreads();
    load_Bhalf(smem, seg, 1, tid);             // W1 lo
    __syncthreads();
    gemm_single(sb + SM_AHI, sb + SM_B, acc, lid, mr);
    __syncthreads();                           // all A/B readers done

    // epilogue 1: H = relu(acc + b1) -> overlay A planes; also stage W2 hi
#pragma unroll
    for (int nt = 0; nt < 16; nt++) {
        int col = nt * 8 + c0l;
        float2 bb = *reinterpret_cast<const float2*>(bb1 + col);
        float x0 = fmaxf(acc[nt][0] + bb.x, 0.f);
        float x1 = fmaxf(acc[nt][1] + bb.y, 0.f);
        float x2 = fmaxf(acc[nt][2] + bb.x, 0.f);
        float x3 = fmaxf(acc[nt][3] + bb.y, 0.f);
        float r0, r1, r2, r3;
        uint32_t oA = a_off(row0, col);
        uint32_t oB = a_off(row0 + 8, col);
        uint32_t h01 = pack_hi(x0, x1, r0, r1);
        uint32_t h23 = pack_hi(x2, x3, r2, r3);
        *reinterpret_cast<uint32_t*>(smem + SM_AHI + oA) = h01;
        *reinterpret_cast<uint32_t*>(smem + SM_ALO + oA) = pack_lo(r0, r1);
        *reinterpret_cast<uint32_t*>(smem + SM_AHI + oB) = h23;
        *reinterpret_cast<uint32_t*>(smem + SM_ALO + oB) = pack_lo(r2, r3);
#pragma unroll
        for (int q = 0; q < 4; q++) acc[nt][q] = 0.f;
    }
    load_Bhalf(smem, 4 + seg, 0, tid);         // W2 hi
    __syncthreads();
    gemm_pair(sb + SM_AHI, sb + SM_ALO, sb + SM_B, acc, lid, mr);
    __syncthreads();
    load_Bhalf(smem, 4 + seg, 1, tid);         // W2 lo
    __syncthreads();
    gemm_single(sb + SM_AHI, sb + SM_B, acc, lid, mr);

    // epilogue 2: Y = (acc + b2) * rsqrt(src deg)
    float s0 = 0.f, s1 = 0.f;
    if (g0 < N) s0 = rsqrtf((float)max(g_cnt[cntbase + g0], 1));
    if (g1 < N) s1 = rsqrtf((float)max(g_cnt[cntbase + g1], 1));
#pragma unroll
    for (int nt = 0; nt < 16; nt++) {
        int col = nt * 8 + c0l;
        float2 bb = *reinterpret_cast<const float2*>(bb2 + col);
        if (g0 < N)
            *reinterpret_cast<float2*>(Y + (size_t)g0 * DIM + col) =
                make_float2((acc[nt][0] + bb.x) * s0, (acc[nt][1] + bb.y) * s0);
        if (g1 < N)
            *reinterpret_cast<float2*>(Y + (size_t)g1 * DIM + col) =
                make_float2((acc[nt][2] + bb.x) * s1, (acc[nt][3] + bb.y) * s1);
    }
}

// ---------------- iter-0 message MLP (standalone; subsequent iters fused) ----------------
__global__ __launch_bounds__(256, 2) void mlp_tc_kernel(
    const float* __restrict__ vt, const float* __restrict__ ct, int V, int C,
    const float* __restrict__ b1, const float* __restrict__ b2,
    float* __restrict__ msgbase, int vtiles) {
    extern __shared__ char smem[];
    const uint32_t sb = smem_u32(smem);

    const int bx = blockIdx.x;
    const bool isv = (bx < vtiles);
    const int local = isv ? bx : bx - vtiles;
    const float* X = isv ? vt : ct;
    const int N = isv ? V : C;

    const int tid = threadIdx.x;
    const int lid = tid & 31;
    const int mr = (tid >> 5) * 16;
    const int rowbase = local * 128;
    const int row0 = mr + (lid >> 2);
    const int c0l = (lid & 3) * 2;
    const int g0 = rowbase + row0;
    const int g1 = g0 + 8;

    float acc[16][4];
#pragma unroll
    for (int pol = 0; pol < 2; pol++) {
        const int seg = (isv ? 0 : 2) + pol;
        float* Y = msgbase + ((seg == 0) ? (size_t)0
                     : (seg == 1) ? (size_t)VMAX * DIM
                     : (seg == 2) ? (size_t)2 * VMAX * DIM
                                  : ((size_t)2 * VMAX + CMAX) * DIM);
        const int cntbase = (seg == 0) ? 0 : (seg == 1) ? VMAX
                          : (seg == 2) ? 2 * VMAX : 2 * VMAX + CMAX;
        __syncthreads();   // prior pol's smem readers done
        run_mlp_pol(smem, sb, X, N, rowbase, seg, b1, b2, Y, cntbase, acc,
                    tid, lid, mr, row0, c0l, g0, g1);
    }
}

// ---------------- fused per-iteration kernel ----------------
// grid = ctiles + vtiles. Per CTA (128 dest rows):
//   upd: seg0 load_A(emb), seg1/2 gather_A(CSR-sum msgs_in), each x (Bh pair + Bl single)
//   epilogue: Y = acc + bias -> emb_out
//   if do_mlp: reload Y from emb_out (CTA-coherent after syncthreads) and run both
//   polarity message MLPs, storing msgs_out scaled by rsqrt(src deg).
__global__ __launch_bounds__(256, 2) void iter_kernel(
    const float* __restrict__ vt, const float* __restrict__ ct, int V, int C, int ctiles,
    const float* __restrict__ cb, const float* __restrict__ vb,
    float* __restrict__ v_out, float* __restrict__ c_out,
    const float* __restrict__ msg_in, float* __restrict__ msg_out,
    const float* __restrict__ b1, const float* __restrict__ b2, int do_mlp) {
    extern __shared__ char smem[];
    const uint32_t sb = smem_u32(smem);

    const int bx = blockIdx.x;
    const bool isc = (bx < ctiles);
    const int local = isc ? bx : bx - ctiles;

    const float* X     = isc ? ct : vt;
    const int N        = isc ? C : V;
    const int slotW    = isc ? 8 : 11;
    const float* bias  = isc ? cb : vb;
    float* Yout        = isc ? c_out : v_out;
    // gather inputs: c-update reads v-messages; v-update reads c-messages
    const float* in_p  = msg_in + (isc ? (size_t)0 : (size_t)2 * VMAX * DIM);
    const float* in_n  = msg_in + (isc ? (size_t)VMAX * DIM : ((size_t)2 * VMAX + CMAX) * DIM);
    const int dbase_p  = isc ? 2 * VMAX : 0;
    const int dbase_n  = isc ? 2 * VMAX + CMAX : VMAX;
    const int mlpseg0  = isc ? 2 : 0;
    float* out_p       = msg_out + (isc ? (size_t)2 * VMAX * DIM : (size_t)0);
    float* out_n       = msg_out + (isc ? ((size_t)2 * VMAX + CMAX) * DIM : (size_t)VMAX * DIM);

    const int tid = threadIdx.x;
    const int lid = tid & 31;
    const int mr = (tid >> 5) * 16;
    const int rowbase = local * 128;
    const int row0 = mr + (lid >> 2);
    const int c0l = (lid & 3) * 2;
    const int g0 = rowbase + row0;
    const int g1 = g0 + 8;

    float acc[16][4];
#pragma unroll
    for (int t = 0; t < 16; t++)
#pragma unroll
        for (int q = 0; q < 4; q++) acc[t][q] = 0.f;

    // ---- update GEMM: K = 384 over [emb | p-agg | n-agg], B in 32KB halves ----
#pragma unroll
    for (int s = 0; s < 3; s++) {
        __syncthreads();           // previous stage's A/B readers done
        if (s == 0)      load_A(smem, X, rowbase, N, tid, 256);
        else if (s == 1) gather_A(smem, in_p, dbase_p, rowbase, N, tid);
        else             gather_A(smem, in_n, dbase_n, rowbase, N, tid);
        load_Bhalf(smem, slotW + s, 0, tid);
        __syncthreads();
        gemm_pair(sb + SM_AHI, sb + SM_ALO, sb + SM_B, acc, lid, mr);
        __syncthreads();
        load_Bhalf(smem, slotW + s, 1, tid);
        __syncthreads();
        gemm_single(sb + SM_AHI, sb + SM_B, acc, lid, mr);
    }

    // ---- epilogue: Y = acc + bias -> global emb_out ----
#pragma unroll
    for (int nt = 0; nt < 16; nt++) {
        int col = nt * 8 + c0l;
        float2 bb = *reinterpret_cast<const float2*>(bias + col);
        if (g0 < N)
            *reinterpret_cast<float2*>(Yout + (size_t)g0 * DIM + col) =
                make_float2(acc[nt][0] + bb.x, acc[nt][1] + bb.y);
        if (g1 < N)
            *reinterpret_cast<float2*>(Yout + (size_t)g1 * DIM + col) =
                make_float2(acc[nt][2] + bb.x, acc[nt][3] + bb.y);
    }
    if (!do_mlp) return;

    // ---- fused next-iteration message MLPs; Y reloaded from emb_out per polarity ----
#pragma unroll
    for (int pol = 0; pol < 2; pol++) {
        const int seg = mlpseg0 + pol;
        float* Y = pol ? out_n : out_p;
        const int cntbase = pol ? dbase_n : dbase_p;   // dest-node deg == next-iter src deg
        __syncthreads();   // prior smem readers done; Y stores visible CTA-wide
        run_mlp_pol(smem, sb, Yout, N, rowbase, seg, b1, b2, Y, cntbase, acc,
                    tid, lid, mr, row0, c0l, g0, g1);
    }
}

// ---------------- host launcher ----------------
extern "C" void kernel_launch(void* const* d_in, const int* in_sizes, int n_in,
                              void* d_out, int out_size) {
    int base = (in_sizes[0] == 1 && in_sizes[1] == 1) ? 2 : 0;
    const int*   v_edge = (const int*)d_in[base + 0];
    const int*   c_edge = (const int*)d_in[base + 1];
    const int*   p_idx  = (const int*)d_in[base + 2];
    const int*   n_idx  = (const int*)d_in[base + 3];
    const float* v_emb  = (const float*)d_in[base + 4];
    const float* c_emb  = (const float*)d_in[base + 5];
    const float* W1     = (const float*)d_in[base + 6];
    const float* b1     = (const float*)d_in[base + 7];
    const float* W2     = (const float*)d_in[base + 8];
    const float* b2     = (const float*)d_in[base + 9];
    const float* cW     = (const float*)d_in[base + 10];
    const float* cb     = (const float*)d_in[base + 11];
    const float* vW     = (const float*)d_in[base + 12];
    const float* vbias  = (const float*)d_in[base + 13];

    const int EP = in_sizes[base + 2];
    const int EN = in_sizes[base + 3];
    const int V  = in_sizes[base + 4] / DIM;
    const int C  = in_sizes[base + 5] / DIM;

    int *pv, *pc, *nv, *nc, *cnt;
    float *msg;
    cudaGetSymbolAddress((void**)&pv,  g_pv);
    cudaGetSymbolAddress((void**)&pc,  g_pc);
    cudaGetSymbolAddress((void**)&nv,  g_nv);
    cudaGetSymbolAddress((void**)&nc,  g_nc);
    cudaGetSymbolAddress((void**)&cnt, g_cnt);
    cudaGetSymbolAddress((void**)&msg, g_msg);

    float* msgbuf[2] = { msg, msg + (size_t)NCNT * DIM };

    cudaFuncSetAttribute(mlp_tc_kernel, cudaFuncAttributeMaxDynamicSharedMemorySize, SM_BYTES);
    cudaFuncSetAttribute(iter_kernel,   cudaFuncAttributeMaxDynamicSharedMemorySize, SM_BYTES);

    // one-time per call: weight prep + CSR build
    prep_kernel<<<(14 * 16384 + 255) / 256, 256>>>(W1, W2, cW, vW);
    cudaMemsetAsync(cnt, 0, (size_t)NCNT * sizeof(int));
    count_kernel<<<(EP + 255) / 256, 256>>>(p_idx, v_edge, c_edge, EP, 0, 2 * VMAX, pv, pc);
    count_kernel<<<(EN + 255) / 256, 256>>>(n_idx, v_edge, c_edge, EN, VMAX, 2 * VMAX + CMAX, nv, nc);
    scan1_kernel<<<SCAN_NBLK, 256>>>();
    scan2_kernel<<<1, 512>>>();
    scan3_kernel<<<(NCNT + 255) / 256, 256>>>();
    fill_kernel<<<(EP + 255) / 256, 256>>>(pv, pc, EP, 0, 2 * VMAX);
    fill_kernel<<<(EN + 255) / 256, 256>>>(nv, nc, EN, VMAX, 2 * VMAX + CMAX);

    // output slab doubles as the embedding history: [5,V,128] then [5,C,128]
    float* out   = (float*)d_out;
    float* out_v = out;
    float* out_c = out + (size_t)(NITER + 1) * V * DIM;
    cudaMemcpyAsync(out_v, v_emb, (size_t)V * DIM * sizeof(float), cudaMemcpyDeviceToDevice);
    cudaMemcpyAsync(out_c, c_emb, (size_t)C * DIM * sizeof(float), cudaMemcpyDeviceToDevice);

    const int vtiles = (V + 127) / 128;
    const int ctiles = (C + 127) / 128;

    // iter-0 messages from the initial embeddings -> buffer 0
    mlp_tc_kernel<<<vtiles + ctiles, 256, SM_BYTES>>>(out_v, out_c, V, C, b1, b2, msgbuf[0], vtiles);

    for (int t = 0; t < NITER; t++) {
        const float* vt = out_v + (size_t)t * V * DIM;
        const float* ct = out_c + (size_t)t * C * DIM;
        iter_kernel<<<ctiles + vtiles, 256, SM_BYTES>>>(
            vt, ct, V, C, ctiles, cb, vbias,
            out_v + (size_t)(t + 1) * V * DIM, out_c + (size_t)(t + 1) * C * DIM,
            msgbuf[t & 1], msgbuf[(t + 1) & 1], b1, b2, (t < NITER - 1) ? 1 : 0);
    }
}